// round 3
// baseline (speedup 1.0000x reference)
#include <cuda_runtime.h>
#include <math.h>

#define B_ 2
#define T_ 2048
#define C_ 1024
#define H_ 16
#define D_ 64
#define BT_ (B_*T_)
#define EPSF 1.1920929e-07f

// Scratch (device globals -- no allocation allowed in kernel_launch)
__device__ float g_qkv[(size_t)BT_*3*C_];   // [4096, 3072]
__device__ float g_q[(size_t)B_*H_*T_*D_];  // [B,H,T,D]
__device__ float g_k[(size_t)B_*H_*T_*D_];
__device__ float g_v[(size_t)B_*H_*T_*D_];
__device__ float g_att[(size_t)BT_*C_];     // [4096, 1024]

// ---------------------------------------------------------------------------
// SGEMM + bias: C[MxN] = A[MxK] * B[KxN] + bias[N]
// 128x128 block tile, BK=16, 256 threads, 8x8 per-thread micro-tile.
// M,N multiples of 128; K multiple of 16 (true for all our shapes).
// ---------------------------------------------------------------------------
__global__ __launch_bounds__(256) void sgemm_bias_kernel(
    const float* __restrict__ A, const float* __restrict__ Bm,
    const float* __restrict__ bias, float* __restrict__ Cm,
    int M, int N, int K)
{
    const int BM = 128, BN = 128, BK = 16;
    __shared__ float As[BK][BM];   // transposed A tile
    __shared__ float Bs[BK][BN];

    int tid = threadIdx.x;
    int tx = tid & 15, ty = tid >> 4;
    int bm = blockIdx.y * BM, bn = blockIdx.x * BN;

    float acc[8][8];
#pragma unroll
    for (int i = 0; i < 8; i++)
#pragma unroll
        for (int j = 0; j < 8; j++) acc[i][j] = 0.0f;

    for (int k0 = 0; k0 < K; k0 += BK) {
        // Load A tile (BM x BK) as float4 along K, store transposed.
#pragma unroll
        for (int i = tid; i < BM * BK / 4; i += 256) {
            int row = i >> 2;
            int c4  = (i & 3) << 2;
            float4 v = *(const float4*)(A + (size_t)(bm + row) * K + k0 + c4);
            As[c4 + 0][row] = v.x;
            As[c4 + 1][row] = v.y;
            As[c4 + 2][row] = v.z;
            As[c4 + 3][row] = v.w;
        }
        // Load B tile (BK x BN) as float4 along N.
#pragma unroll
        for (int i = tid; i < BK * BN / 4; i += 256) {
            int row = i >> 5;
            int c4  = (i & 31) << 2;
            *(float4*)(&Bs[row][c4]) =
                *(const float4*)(Bm + (size_t)(k0 + row) * N + bn + c4);
        }
        __syncthreads();

#pragma unroll
        for (int kk = 0; kk < BK; kk++) {
            float a[8], b[8];
            *(float4*)(a)     = *(float4*)(&As[kk][ty * 8]);
            *(float4*)(a + 4) = *(float4*)(&As[kk][ty * 8 + 4]);
            *(float4*)(b)     = *(float4*)(&Bs[kk][tx * 8]);
            *(float4*)(b + 4) = *(float4*)(&Bs[kk][tx * 8 + 4]);
#pragma unroll
            for (int i = 0; i < 8; i++)
#pragma unroll
                for (int j = 0; j < 8; j++)
                    acc[i][j] += a[i] * b[j];
        }
        __syncthreads();
    }

#pragma unroll
    for (int i = 0; i < 8; i++) {
        int r = bm + ty * 8 + i;
#pragma unroll
        for (int j = 0; j < 8; j += 4) {
            int c = bn + tx * 8 + j;
            float4 o;
            o.x = acc[i][j + 0] + bias[c + 0];
            o.y = acc[i][j + 1] + bias[c + 1];
            o.z = acc[i][j + 2] + bias[c + 2];
            o.w = acc[i][j + 3] + bias[c + 3];
            *(float4*)(Cm + (size_t)r * N + c) = o;
        }
    }
}

// ---------------------------------------------------------------------------
// RMSNorm(q,k) + rotary(q,k) + scatter q,k,v from qkv[4096,3072]
// into [B,H,T,D] layout. One warp per (b,t,h); lane handles d and d+32.
// ---------------------------------------------------------------------------
__global__ __launch_bounds__(256) void rmsrot_kernel(
    const float* __restrict__ qkv, const float* __restrict__ cosT,
    const float* __restrict__ sinT, float* __restrict__ Q,
    float* __restrict__ K, float* __restrict__ V)
{
    int lane = threadIdx.x & 31;
    int row  = blockIdx.x * 8 + (threadIdx.x >> 5);  // 0 .. B*T*H-1
    int h = row & (H_ - 1);
    int t = (row >> 4) & (T_ - 1);
    int b = row >> 15;  // T_*H_ = 32768

    const float* src = qkv + (size_t)(b * T_ + t) * (3 * C_) + h * D_;
    float q0 = src[lane],        q1 = src[lane + 32];
    float k0 = src[C_ + lane],   k1 = src[C_ + lane + 32];
    float v0 = src[2*C_ + lane], v1 = src[2*C_ + lane + 32];

    float sq = q0 * q0 + q1 * q1;
    float sk = k0 * k0 + k1 * k1;
#pragma unroll
    for (int off = 16; off; off >>= 1) {
        sq += __shfl_xor_sync(0xffffffffu, sq, off);
        sk += __shfl_xor_sync(0xffffffffu, sk, off);
    }
    float rq = rsqrtf(sq * (1.0f / 64.0f) + EPSF);
    float rk = rsqrtf(sk * (1.0f / 64.0f) + EPSF);
    q0 *= rq; q1 *= rq; k0 *= rk; k1 *= rk;

    float c0 = cosT[t * D_ + lane], c1 = cosT[t * D_ + lane + 32];
    float s0 = sinT[t * D_ + lane], s1 = sinT[t * D_ + lane + 32];

    float qo0 = q0 * c0 - q1 * s0;
    float qo1 = q1 * c1 + q0 * s1;
    float ko0 = k0 * c0 - k1 * s0;
    float ko1 = k1 * c1 + k0 * s1;

    size_t dst = ((size_t)(b * H_ + h) * T_ + t) * D_;
    Q[dst + lane] = qo0; Q[dst + lane + 32] = qo1;
    K[dst + lane] = ko0; K[dst + lane + 32] = ko1;
    V[dst + lane] = v0;  V[dst + lane + 32] = v1;
}

// ---------------------------------------------------------------------------
// Causal flash attention, fp32. 64 query rows x 64 key cols per tile.
// 256 threads: (ty,tx) = 16x16 grid, each thread owns a 4x4 micro-tile
// of S/P and a 4(rows)x4(head-dim) micro-tile of O.
// Output written directly as [b, t, h*D+d] = [4096, 1024] for the proj GEMM.
// ---------------------------------------------------------------------------
__global__ __launch_bounds__(256) void attn_kernel(
    const float* __restrict__ Q, const float* __restrict__ K,
    const float* __restrict__ V, float* __restrict__ Y)
{
    extern __shared__ float sm[];
    float* Qs = sm;                 // [64][64]
    float* Ks = Qs + 64 * 64;       // [64][65] (padded)
    float* Vs = Ks + 64 * 65;       // [64][64]
    float* Ps = Vs + 64 * 64;       // [64][64]

    const float scale = 0.125f;     // 1/sqrt(64)
    int tid = threadIdx.x;
    int tx = tid & 15, ty = tid >> 4;
    int i0 = blockIdx.x * 64;
    int bh = blockIdx.y;            // b*H + h
    size_t base = (size_t)bh * T_ * D_;

    // Load Q tile
    for (int i = tid; i < 64 * 64; i += 256) {
        int r = i >> 6, d = i & 63;
        Qs[r * 64 + d] = Q[base + (size_t)(i0 + r) * D_ + d];
    }

    float m[4], l[4], o[4][4];
#pragma unroll
    for (int ii = 0; ii < 4; ii++) {
        m[ii] = -1e30f; l[ii] = 0.0f;
#pragma unroll
        for (int jj = 0; jj < 4; jj++) o[ii][jj] = 0.0f;
    }
    __syncthreads();

    for (int j0 = 0; j0 <= i0; j0 += 64) {
        // Load K/V tiles
        for (int i = tid; i < 64 * 64; i += 256) {
            int r = i >> 6, d = i & 63;
            Ks[r * 65 + d] = K[base + (size_t)(j0 + r) * D_ + d];
            Vs[r * 64 + d] = V[base + (size_t)(j0 + r) * D_ + d];
        }
        __syncthreads();

        // S = scale * Q K^T
        float s[4][4];
#pragma unroll
        for (int ii = 0; ii < 4; ii++)
#pragma unroll
            for (int jj = 0; jj < 4; jj++) s[ii][jj] = 0.0f;

#pragma unroll 8
        for (int k = 0; k < 64; k++) {
            float a[4], b[4];
#pragma unroll
            for (int ii = 0; ii < 4; ii++) a[ii] = Qs[(ty * 4 + ii) * 64 + k];
#pragma unroll
            for (int jj = 0; jj < 4; jj++) b[jj] = Ks[(tx * 4 + jj) * 65 + k];
#pragma unroll
            for (int ii = 0; ii < 4; ii++)
#pragma unroll
                for (int jj = 0; jj < 4; jj++)
                    s[ii][jj] += a[ii] * b[jj];
        }

        bool diag = (j0 == i0);
#pragma unroll
        for (int ii = 0; ii < 4; ii++)
#pragma unroll
            for (int jj = 0; jj < 4; jj++) {
                s[ii][jj] *= scale;
                if (diag && (tx * 4 + jj > ty * 4 + ii)) s[ii][jj] = -1e30f;
            }

        // Online softmax
        float p[4][4];
#pragma unroll
        for (int ii = 0; ii < 4; ii++) {
            float mt = fmaxf(fmaxf(s[ii][0], s[ii][1]), fmaxf(s[ii][2], s[ii][3]));
#pragma unroll
            for (int off = 8; off; off >>= 1)
                mt = fmaxf(mt, __shfl_xor_sync(0xffffffffu, mt, off, 16));
            float mn = fmaxf(m[ii], mt);
            float alpha = __expf(m[ii] - mn);
            m[ii] = mn;
            float sum = 0.0f;
#pragma unroll
            for (int jj = 0; jj < 4; jj++) {
                p[ii][jj] = __expf(s[ii][jj] - mn);
                sum += p[ii][jj];
            }
#pragma unroll
            for (int off = 8; off; off >>= 1)
                sum += __shfl_xor_sync(0xffffffffu, sum, off, 16);
            l[ii] = l[ii] * alpha + sum;
#pragma unroll
            for (int jj = 0; jj < 4; jj++) o[ii][jj] *= alpha;
        }

        // Write P to smem
#pragma unroll
        for (int ii = 0; ii < 4; ii++)
#pragma unroll
            for (int jj = 0; jj < 4; jj++)
                Ps[(ty * 4 + ii) * 64 + tx * 4 + jj] = p[ii][jj];
        __syncthreads();

        // O += P @ V
#pragma unroll 8
        for (int k = 0; k < 64; k++) {
            float pr[4];
#pragma unroll
            for (int ii = 0; ii < 4; ii++) pr[ii] = Ps[(ty * 4 + ii) * 64 + k];
            float4 vv = *(float4*)(&Vs[k * 64 + tx * 4]);
#pragma unroll
            for (int ii = 0; ii < 4; ii++) {
                o[ii][0] += pr[ii] * vv.x;
                o[ii][1] += pr[ii] * vv.y;
                o[ii][2] += pr[ii] * vv.z;
                o[ii][3] += pr[ii] * vv.w;
            }
        }
        __syncthreads();
    }

    // Epilogue: normalize and write to [b, t, h*D + d]
    int b = bh >> 4, h = bh & 15;
#pragma unroll
    for (int ii = 0; ii < 4; ii++) {
        float inv = 1.0f / l[ii];
        int r = i0 + ty * 4 + ii;
        size_t off = (size_t)(b * T_ + r) * C_ + h * D_ + tx * 4;
        float4 ov;
        ov.x = o[ii][0] * inv;
        ov.y = o[ii][1] * inv;
        ov.z = o[ii][2] * inv;
        ov.w = o[ii][3] * inv;
        *(float4*)(Y + off) = ov;
    }
}

// ---------------------------------------------------------------------------

extern "C" void kernel_launch(void* const* d_in, const int* in_sizes, int n_in,
                              void* d_out, int out_size)
{
    const float* x      = (const float*)d_in[0];
    const float* cosT   = (const float*)d_in[1];
    const float* sinT   = (const float*)d_in[2];
    const float* W_attn = (const float*)d_in[3];
    const float* b_attn = (const float*)d_in[4];
    const float* W_proj = (const float*)d_in[5];
    const float* b_proj = (const float*)d_in[6];
    float* out = (float*)d_out;

    float *qkv, *q, *k, *v, *att;
    cudaGetSymbolAddress((void**)&qkv, g_qkv);
    cudaGetSymbolAddress((void**)&q,   g_q);
    cudaGetSymbolAddress((void**)&k,   g_k);
    cudaGetSymbolAddress((void**)&v,   g_v);
    cudaGetSymbolAddress((void**)&att, g_att);

    // 1) QKV GEMM: [4096,1024] @ [1024,3072] + b_attn
    sgemm_bias_kernel<<<dim3(3 * C_ / 128, BT_ / 128), 256>>>(
        x, W_attn, b_attn, qkv, BT_, 3 * C_, C_);

    // 2) RMSNorm + rotary + scatter to [B,H,T,D]
    rmsrot_kernel<<<(B_ * T_ * H_) / 8, 256>>>(qkv, cosT, sinT, q, k, v);

    // 3) Causal flash attention
    const int ATTN_SMEM = (64 * 64 + 64 * 65 + 64 * 64 + 64 * 64) * 4;  // 65792
    cudaFuncSetAttribute(attn_kernel,
                         cudaFuncAttributeMaxDynamicSharedMemorySize, ATTN_SMEM);
    attn_kernel<<<dim3(T_ / 64, B_ * H_), 256, ATTN_SMEM>>>(q, k, v, att);

    // 4) Proj GEMM: [4096,1024] @ [1024,1024] + b_proj
    sgemm_bias_kernel<<<dim3(C_ / 128, BT_ / 128), 256>>>(
        att, W_proj, b_proj, out, BT_, C_, C_);
}

// round 9
// speedup vs baseline: 1.4250x; 1.4250x over previous
#include <cuda_runtime.h>
#include <cuda_bf16.h>
#include <cstdint>
#include <math.h>

#define B_ 2
#define T_ 2048
#define C_ 1024
#define H_ 16
#define D_ 64
#define BT_ (B_*T_)
#define EPSF 1.1920929e-07f

// ---------------- scratch (device globals; no allocs allowed) ---------------
__device__ float g_qkv[(size_t)BT_*3*C_];          // [4096, 3072]
__device__ float g_q[(size_t)B_*H_*T_*D_];
__device__ float g_k[(size_t)B_*H_*T_*D_];
__device__ float g_v[(size_t)B_*H_*T_*D_];
__device__ float g_att[(size_t)BT_*C_];            // [4096, 1024]

__device__ __nv_bfloat16 g_xh[(size_t)BT_*C_];     // x split
__device__ __nv_bfloat16 g_xl[(size_t)BT_*C_];
__device__ __nv_bfloat16 g_wah[(size_t)3*C_*C_];   // W_attn^T split  [3072,1024]
__device__ __nv_bfloat16 g_wal[(size_t)3*C_*C_];
__device__ __nv_bfloat16 g_wph[(size_t)C_*C_];     // W_proj^T split  [1024,1024]
__device__ __nv_bfloat16 g_wpl[(size_t)C_*C_];
__device__ __nv_bfloat16 g_ath[(size_t)BT_*C_];    // attention out split
__device__ __nv_bfloat16 g_atl[(size_t)BT_*C_];

// ---------------------------- helpers ---------------------------------------
__device__ __forceinline__ uint32_t smem_u32(const void* p) {
    uint32_t a;
    asm("{ .reg .u64 t; cvta.to.shared.u64 t, %1; cvt.u32.u64 %0, t; }"
        : "=r"(a) : "l"(p));
    return a;
}
__device__ __forceinline__ void ldsm_x4(uint32_t* r, uint32_t addr) {
    asm volatile("ldmatrix.sync.aligned.m8n8.x4.shared.b16 {%0,%1,%2,%3}, [%4];"
                 : "=r"(r[0]), "=r"(r[1]), "=r"(r[2]), "=r"(r[3]) : "r"(addr));
}
__device__ __forceinline__ void ldsm_x2(uint32_t* r, uint32_t addr) {
    asm volatile("ldmatrix.sync.aligned.m8n8.x2.shared.b16 {%0,%1}, [%2];"
                 : "=r"(r[0]), "=r"(r[1]) : "r"(addr));
}
__device__ __forceinline__ void mma_bf16(float* c, const uint32_t* a,
                                         const uint32_t* b) {
    asm volatile(
        "mma.sync.aligned.m16n8k16.row.col.f32.bf16.bf16.f32 "
        "{%0,%1,%2,%3}, {%4,%5,%6,%7}, {%8,%9}, {%0,%1,%2,%3};"
        : "+f"(c[0]), "+f"(c[1]), "+f"(c[2]), "+f"(c[3])
        : "r"(a[0]), "r"(a[1]), "r"(a[2]), "r"(a[3]), "r"(b[0]), "r"(b[1]));
}
__device__ __forceinline__ void cp_async16(uint32_t dst, const void* src) {
    asm volatile("cp.async.cg.shared.global [%0], [%1], 16;"
                 :: "r"(dst), "l"(src));
}

// ---------------------------------------------------------------------------
// fp32 -> (hi, lo) bf16 split, elementwise, float4 per thread
// ---------------------------------------------------------------------------
__global__ __launch_bounds__(256) void split_kernel(
    const float* __restrict__ x, __nv_bfloat16* __restrict__ hi,
    __nv_bfloat16* __restrict__ lo)
{
    int i = blockIdx.x * 256 + threadIdx.x;
    float4 v = ((const float4*)x)[i];
    __nv_bfloat16 h0 = __float2bfloat16(v.x), h1 = __float2bfloat16(v.y);
    __nv_bfloat16 h2 = __float2bfloat16(v.z), h3 = __float2bfloat16(v.w);
    __nv_bfloat162 a, b, c, d;
    a.x = h0; a.y = h1; b.x = h2; b.y = h3;
    c.x = __float2bfloat16(v.x - __bfloat162float(h0));
    c.y = __float2bfloat16(v.y - __bfloat162float(h1));
    d.x = __float2bfloat16(v.z - __bfloat162float(h2));
    d.y = __float2bfloat16(v.w - __bfloat162float(h3));
    ((__nv_bfloat162*)hi)[i * 2]     = a;
    ((__nv_bfloat162*)hi)[i * 2 + 1] = b;
    ((__nv_bfloat162*)lo)[i * 2]     = c;
    ((__nv_bfloat162*)lo)[i * 2 + 1] = d;
}

// ---------------------------------------------------------------------------
// W [K,N] fp32 -> W^T [N,K] split bf16 (32x32 smem transpose tiles)
// ---------------------------------------------------------------------------
__global__ __launch_bounds__(256) void splitT_kernel(
    const float* __restrict__ W, __nv_bfloat16* __restrict__ Th,
    __nv_bfloat16* __restrict__ Tl, int K, int N)
{
    __shared__ float tile[32][33];
    int n0 = blockIdx.x * 32, k0 = blockIdx.y * 32;
    int tx = threadIdx.x & 31, ty = threadIdx.x >> 5;
#pragma unroll
    for (int j = 0; j < 4; j++) {
        int r = ty + j * 8;
        tile[r][tx] = W[(size_t)(k0 + r) * N + n0 + tx];
    }
    __syncthreads();
#pragma unroll
    for (int j = 0; j < 4; j++) {
        int r = ty + j * 8;
        float v = tile[tx][r];
        __nv_bfloat16 h = __float2bfloat16(v);
        size_t o = (size_t)(n0 + r) * K + k0 + tx;
        Th[o] = h;
        Tl[o] = __float2bfloat16(v - __bfloat162float(h));
    }
}

// ---------------------------------------------------------------------------
// mma.sync bf16-split GEMM + bias: C[M,N] = A[M,K]*B[K,N] + bias
//   Ah/Al [M,K] row-major bf16; Bh/Bl PRE-TRANSPOSED [N,K] bf16.
//   CTA 128x128, BK=32, 2-stage cp.async pipeline.
//   8 warps in 2(m)x4(n) grid; warp tile 64x32 = 4x4 m16n8 mma tiles.
//   Smem tiles: [rows][32 bf16] with 80-byte row stride (conflict-free
//   ldmatrix: r*80 mod 128 hits all eight 16B slots).
// ---------------------------------------------------------------------------
#define TILE_B 10240          // 128 rows * 80 bytes
#define STAGE_B (4 * TILE_B)  // Ah, Al, Bh, Bl

__global__ __launch_bounds__(256, 1) void gemm_mma_kernel(
    const __nv_bfloat16* __restrict__ Ah, const __nv_bfloat16* __restrict__ Al,
    const __nv_bfloat16* __restrict__ Bh, const __nv_bfloat16* __restrict__ Bl,
    const float* __restrict__ bias, float* __restrict__ Cm,
    int M, int N, int K)
{
    extern __shared__ __align__(128) char sm[];
    const int tid = threadIdx.x;
    const int wid = tid >> 5, lane = tid & 31;
    const int wm = wid >> 2, wn = wid & 3;
    const int bm = blockIdx.y * 128, bn = blockIdx.x * 128;
    const int NCH = K >> 5;

    float acc[4][4][4];
#pragma unroll
    for (int mt = 0; mt < 4; mt++)
#pragma unroll
        for (int nt = 0; nt < 4; nt++)
#pragma unroll
            for (int r = 0; r < 4; r++) acc[mt][nt][r] = 0.0f;

    const __nv_bfloat16* srcs[4] = {Ah, Al, Bh, Bl};

    // --- stage loader: 4 tiles x 512 16B chunks, 8 per thread -------------
    auto load_stage = [&](int s, int k0) {
        char* base = sm + s * STAGE_B;
#pragma unroll
        for (int t = 0; t < 4; t++) {
            const __nv_bfloat16* src = srcs[t];
            int rbase = (t < 2) ? bm : bn;
#pragma unroll
            for (int j = 0; j < 2; j++) {
                int c = tid + (j << 8);          // 0..511
                int row = c >> 2, kc = c & 3;
                uint32_t dst = smem_u32(base + t * TILE_B + row * 80 + kc * 16);
                cp_async16(dst, src + (size_t)(rbase + row) * K + k0 + kc * 8);
            }
        }
        asm volatile("cp.async.commit_group;" ::: "memory");
    };

    load_stage(0, 0);

#pragma unroll 1
    for (int i = 0; i < NCH; i++) {
        if (i + 1 < NCH) {
            load_stage((i + 1) & 1, (i + 1) << 5);
            asm volatile("cp.async.wait_group 1;" ::: "memory");
        } else {
            asm volatile("cp.async.wait_group 0;" ::: "memory");
        }
        __syncthreads();

        char* base = sm + (i & 1) * STAGE_B;
        uint32_t aAh = smem_u32(base);
        uint32_t aAl = aAh + TILE_B;
        uint32_t aBh = aAh + 2 * TILE_B;
        uint32_t aBl = aAh + 3 * TILE_B;

#pragma unroll
        for (int ks = 0; ks < 2; ks++) {
            uint32_t ah[4][4], al[4][4], bh[4][2], bl[4][2];
            int arow = wm * 64 + (lane & 15);
            int acol = ks * 32 + ((lane >> 4) << 4);        // bytes
            int brow = wn * 32 + (lane & 7);
            int bcol = ks * 32 + (((lane >> 3) & 1) << 4);  // bytes
#pragma unroll
            for (int mt = 0; mt < 4; mt++) {
                uint32_t off = (uint32_t)(arow + mt * 16) * 80 + acol;
                ldsm_x4(ah[mt], aAh + off);
                ldsm_x4(al[mt], aAl + off);
            }
#pragma unroll
            for (int nt = 0; nt < 4; nt++) {
                uint32_t off = (uint32_t)(brow + nt * 8) * 80 + bcol;
                ldsm_x2(bh[nt], aBh + off);
                ldsm_x2(bl[nt], aBl + off);
            }
#pragma unroll
            for (int mt = 0; mt < 4; mt++)
#pragma unroll
                for (int nt = 0; nt < 4; nt++) {
                    mma_bf16(acc[mt][nt], ah[mt], bh[nt]);
                    mma_bf16(acc[mt][nt], ah[mt], bl[nt]);
                    mma_bf16(acc[mt][nt], al[mt], bh[nt]);
                }
        }
        __syncthreads();
    }

    // epilogue: thread (lane) owns rows g, g+8 and 2 cols per tile
    int gq = lane >> 2, tr = lane & 3;
#pragma unroll
    for (int mt = 0; mt < 4; mt++) {
        int r0 = bm + wm * 64 + mt * 16 + gq;
#pragma unroll
        for (int nt = 0; nt < 4; nt++) {
            int col = bn + wn * 32 + nt * 8 + tr * 2;
            float bx = bias[col], by = bias[col + 1];
            float2 v0 = {acc[mt][nt][0] + bx, acc[mt][nt][1] + by};
            float2 v1 = {acc[mt][nt][2] + bx, acc[mt][nt][3] + by};
            *(float2*)(Cm + (size_t)r0 * N + col)       = v0;
            *(float2*)(Cm + (size_t)(r0 + 8) * N + col) = v1;
        }
    }
}

// ---------------------------------------------------------------------------
// RMSNorm + rotary + scatter
// ---------------------------------------------------------------------------
__global__ __launch_bounds__(256) void rmsrot_kernel(
    const float* __restrict__ qkv, const float* __restrict__ cosT,
    const float* __restrict__ sinT, float* __restrict__ Q,
    float* __restrict__ K, float* __restrict__ V)
{
    int lane = threadIdx.x & 31;
    int row  = blockIdx.x * 8 + (threadIdx.x >> 5);
    int h = row & (H_ - 1);
    int t = (row >> 4) & (T_ - 1);
    int b = row >> 15;

    const float* src = qkv + (size_t)(b * T_ + t) * (3 * C_) + h * D_;
    float q0 = src[lane],        q1 = src[lane + 32];
    float k0 = src[C_ + lane],   k1 = src[C_ + lane + 32];
    float v0 = src[2*C_ + lane], v1 = src[2*C_ + lane + 32];

    float sq = q0 * q0 + q1 * q1;
    float sk = k0 * k0 + k1 * k1;
#pragma unroll
    for (int off = 16; off; off >>= 1) {
        sq += __shfl_xor_sync(0xffffffffu, sq, off);
        sk += __shfl_xor_sync(0xffffffffu, sk, off);
    }
    float rq = rsqrtf(sq * (1.0f / 64.0f) + EPSF);
    float rk = rsqrtf(sk * (1.0f / 64.0f) + EPSF);
    q0 *= rq; q1 *= rq; k0 *= rk; k1 *= rk;

    float c0 = cosT[t * D_ + lane], c1 = cosT[t * D_ + lane + 32];
    float s0 = sinT[t * D_ + lane], s1 = sinT[t * D_ + lane + 32];

    float qo0 = q0 * c0 - q1 * s0;
    float qo1 = q1 * c1 + q0 * s1;
    float ko0 = k0 * c0 - k1 * s0;
    float ko1 = k1 * c1 + k0 * s1;

    size_t dst = ((size_t)(b * H_ + h) * T_ + t) * D_;
    Q[dst + lane] = qo0; Q[dst + lane + 32] = qo1;
    K[dst + lane] = ko0; K[dst + lane + 32] = ko1;
    V[dst + lane] = v0;  V[dst + lane + 32] = v1;
}

// ---------------------------------------------------------------------------
// Causal flash attention, fp32 (unchanged)
// ---------------------------------------------------------------------------
__global__ __launch_bounds__(256) void attn_kernel(
    const float* __restrict__ Q, const float* __restrict__ K,
    const float* __restrict__ V, float* __restrict__ Y)
{
    extern __shared__ float smf[];
    float* Qs = smf;
    float* Ks = Qs + 64 * 64;
    float* Vs = Ks + 64 * 65;
    float* Ps = Vs + 64 * 64;

    const float scale = 0.125f;
    int tid = threadIdx.x;
    int tx = tid & 15, ty = tid >> 4;
    int i0 = blockIdx.x * 64;
    int bh = blockIdx.y;
    size_t base = (size_t)bh * T_ * D_;

    for (int i = tid; i < 64 * 64; i += 256) {
        int r = i >> 6, d = i & 63;
        Qs[r * 64 + d] = Q[base + (size_t)(i0 + r) * D_ + d];
    }

    float m[4], l[4], o[4][4];
#pragma unroll
    for (int ii = 0; ii < 4; ii++) {
        m[ii] = -1e30f; l[ii] = 0.0f;
#pragma unroll
        for (int jj = 0; jj < 4; jj++) o[ii][jj] = 0.0f;
    }
    __syncthreads();

    for (int j0 = 0; j0 <= i0; j0 += 64) {
        for (int i = tid; i < 64 * 64; i += 256) {
            int r = i >> 6, d = i & 63;
            Ks[r * 65 + d] = K[base + (size_t)(j0 + r) * D_ + d];
            Vs[r * 64 + d] = V[base + (size_t)(j0 + r) * D_ + d];
        }
        __syncthreads();

        float s[4][4];
#pragma unroll
        for (int ii = 0; ii < 4; ii++)
#pragma unroll
            for (int jj = 0; jj < 4; jj++) s[ii][jj] = 0.0f;

#pragma unroll 8
        for (int k = 0; k < 64; k++) {
            float a[4], b[4];
#pragma unroll
            for (int ii = 0; ii < 4; ii++) a[ii] = Qs[(ty * 4 + ii) * 64 + k];
#pragma unroll
            for (int jj = 0; jj < 4; jj++) b[jj] = Ks[(tx * 4 + jj) * 65 + k];
#pragma unroll
            for (int ii = 0; ii < 4; ii++)
#pragma unroll
                for (int jj = 0; jj < 4; jj++)
                    s[ii][jj] += a[ii] * b[jj];
        }

        bool diag = (j0 == i0);
#pragma unroll
        for (int ii = 0; ii < 4; ii++)
#pragma unroll
            for (int jj = 0; jj < 4; jj++) {
                s[ii][jj] *= scale;
                if (diag && (tx * 4 + jj > ty * 4 + ii)) s[ii][jj] = -1e30f;
            }

        float p[4][4];
#pragma unroll
        for (int ii = 0; ii < 4; ii++) {
            float mt = fmaxf(fmaxf(s[ii][0], s[ii][1]), fmaxf(s[ii][2], s[ii][3]));
#pragma unroll
            for (int off = 8; off; off >>= 1)
                mt = fmaxf(mt, __shfl_xor_sync(0xffffffffu, mt, off, 16));
            float mn = fmaxf(m[ii], mt);
            float alpha = __expf(m[ii] - mn);
            m[ii] = mn;
            float sum = 0.0f;
#pragma unroll
            for (int jj = 0; jj < 4; jj++) {
                p[ii][jj] = __expf(s[ii][jj] - mn);
                sum += p[ii][jj];
            }
#pragma unroll
            for (int off = 8; off; off >>= 1)
                sum += __shfl_xor_sync(0xffffffffu, sum, off, 16);
            l[ii] = l[ii] * alpha + sum;
#pragma unroll
            for (int jj = 0; jj < 4; jj++) o[ii][jj] *= alpha;
        }

#pragma unroll
        for (int ii = 0; ii < 4; ii++)
#pragma unroll
            for (int jj = 0; jj < 4; jj++)
                Ps[(ty * 4 + ii) * 64 + tx * 4 + jj] = p[ii][jj];
        __syncthreads();

#pragma unroll 8
        for (int k = 0; k < 64; k++) {
            float pr[4];
#pragma unroll
            for (int ii = 0; ii < 4; ii++) pr[ii] = Ps[(ty * 4 + ii) * 64 + k];
            float4 vv = *(float4*)(&Vs[k * 64 + tx * 4]);
#pragma unroll
            for (int ii = 0; ii < 4; ii++) {
                o[ii][0] += pr[ii] * vv.x;
                o[ii][1] += pr[ii] * vv.y;
                o[ii][2] += pr[ii] * vv.z;
                o[ii][3] += pr[ii] * vv.w;
            }
        }
        __syncthreads();
    }

    int b = bh >> 4, h = bh & 15;
#pragma unroll
    for (int ii = 0; ii < 4; ii++) {
        float inv = 1.0f / l[ii];
        int r = i0 + ty * 4 + ii;
        size_t off = (size_t)(b * T_ + r) * C_ + h * D_ + tx * 4;
        float4 ov;
        ov.x = o[ii][0] * inv;
        ov.y = o[ii][1] * inv;
        ov.z = o[ii][2] * inv;
        ov.w = o[ii][3] * inv;
        *(float4*)(Y + off) = ov;
    }
}

// ---------------------------------------------------------------------------

extern "C" void kernel_launch(void* const* d_in, const int* in_sizes, int n_in,
                              void* d_out, int out_size)
{
    const float* x      = (const float*)d_in[0];
    const float* cosT   = (const float*)d_in[1];
    const float* sinT   = (const float*)d_in[2];
    const float* W_attn = (const float*)d_in[3];
    const float* b_attn = (const float*)d_in[4];
    const float* W_proj = (const float*)d_in[5];
    const float* b_proj = (const float*)d_in[6];
    float* out = (float*)d_out;

    float *qkv, *q, *k, *v, *att;
    __nv_bfloat16 *xh, *xl, *wah, *wal, *wph, *wpl, *ath, *atl;
    cudaGetSymbolAddress((void**)&qkv, g_qkv);
    cudaGetSymbolAddress((void**)&q,   g_q);
    cudaGetSymbolAddress((void**)&k,   g_k);
    cudaGetSymbolAddress((void**)&v,   g_v);
    cudaGetSymbolAddress((void**)&att, g_att);
    cudaGetSymbolAddress((void**)&xh,  g_xh);
    cudaGetSymbolAddress((void**)&xl,  g_xl);
    cudaGetSymbolAddress((void**)&wah, g_wah);
    cudaGetSymbolAddress((void**)&wal, g_wal);
    cudaGetSymbolAddress((void**)&wph, g_wph);
    cudaGetSymbolAddress((void**)&wpl, g_wpl);
    cudaGetSymbolAddress((void**)&ath, g_ath);
    cudaGetSymbolAddress((void**)&atl, g_atl);

    const int GEMM_SMEM = 2 * STAGE_B;  // 81920
    cudaFuncSetAttribute(gemm_mma_kernel,
                         cudaFuncAttributeMaxDynamicSharedMemorySize, GEMM_SMEM);

    // 0a) split x -> bf16 hi/lo
    split_kernel<<<BT_ * C_ / 1024, 256>>>(x, xh, xl);
    // 0b) transpose + split weights
    splitT_kernel<<<dim3(3 * C_ / 32, C_ / 32), 256>>>(W_attn, wah, wal, C_, 3 * C_);
    splitT_kernel<<<dim3(C_ / 32, C_ / 32), 256>>>(W_proj, wph, wpl, C_, C_);

    // 1) QKV GEMM (tensor cores via mma.sync): [4096,1024] @ [1024,3072]
    gemm_mma_kernel<<<dim3(3 * C_ / 128, BT_ / 128), 256, GEMM_SMEM>>>(
        xh, xl, wah, wal, b_attn, qkv, BT_, 3 * C_, C_);

    // 2) RMSNorm + rotary + scatter
    rmsrot_kernel<<<(B_ * T_ * H_) / 8, 256>>>(qkv, cosT, sinT, q, k, v);

    // 3) Causal flash attention (fp32)
    const int ATTN_SMEM = (64 * 64 + 64 * 65 + 64 * 64 + 64 * 64) * 4;
    cudaFuncSetAttribute(attn_kernel,
                         cudaFuncAttributeMaxDynamicSharedMemorySize, ATTN_SMEM);
    attn_kernel<<<dim3(T_ / 64, B_ * H_), 256, ATTN_SMEM>>>(q, k, v, att);

    // 4) split attention output, then proj GEMM
    split_kernel<<<BT_ * C_ / 1024, 256>>>(att, ath, atl);
    gemm_mma_kernel<<<dim3(C_ / 128, BT_ / 128), 256, GEMM_SMEM>>>(
        ath, atl, wph, wpl, b_proj, out, BT_, C_, C_);
}

// round 13
// speedup vs baseline: 2.4655x; 1.7302x over previous
#include <cuda_runtime.h>
#include <cuda_bf16.h>
#include <cstdint>
#include <math.h>

#define B_ 2
#define T_ 2048
#define C_ 1024
#define H_ 16
#define D_ 64
#define BT_ (B_*T_)
#define EPSF 1.1920929e-07f

// ---------------- scratch (device globals; no allocs allowed) ---------------
__device__ float g_qkv[(size_t)BT_*3*C_];          // [4096, 3072]

__device__ __nv_bfloat16 g_xh[(size_t)BT_*C_];     // x split
__device__ __nv_bfloat16 g_xl[(size_t)BT_*C_];
__device__ __nv_bfloat16 g_wah[(size_t)3*C_*C_];   // W_attn^T split  [3072,1024]
__device__ __nv_bfloat16 g_wal[(size_t)3*C_*C_];
__device__ __nv_bfloat16 g_wph[(size_t)C_*C_];     // W_proj^T split  [1024,1024]
__device__ __nv_bfloat16 g_wpl[(size_t)C_*C_];

__device__ __nv_bfloat16 g_qh[(size_t)B_*H_*T_*D_];  // Q/K/V split [B,H,T,D]
__device__ __nv_bfloat16 g_ql[(size_t)B_*H_*T_*D_];
__device__ __nv_bfloat16 g_kh[(size_t)B_*H_*T_*D_];
__device__ __nv_bfloat16 g_kl[(size_t)B_*H_*T_*D_];
__device__ __nv_bfloat16 g_vh[(size_t)B_*H_*T_*D_];
__device__ __nv_bfloat16 g_vl[(size_t)B_*H_*T_*D_];

__device__ __nv_bfloat16 g_ath[(size_t)BT_*C_];    // attention out split [4096,1024]
__device__ __nv_bfloat16 g_atl[(size_t)BT_*C_];

// ---------------------------- helpers ---------------------------------------
__device__ __forceinline__ uint32_t smem_u32(const void* p) {
    uint32_t a;
    asm("{ .reg .u64 t; cvta.to.shared.u64 t, %1; cvt.u32.u64 %0, t; }"
        : "=r"(a) : "l"(p));
    return a;
}
__device__ __forceinline__ void ldsm_x4(uint32_t* r, uint32_t addr) {
    asm volatile("ldmatrix.sync.aligned.m8n8.x4.shared.b16 {%0,%1,%2,%3}, [%4];"
                 : "=r"(r[0]), "=r"(r[1]), "=r"(r[2]), "=r"(r[3]) : "r"(addr));
}
__device__ __forceinline__ void ldsm_x4_t(uint32_t* r, uint32_t addr) {
    asm volatile("ldmatrix.sync.aligned.m8n8.x4.trans.shared.b16 {%0,%1,%2,%3}, [%4];"
                 : "=r"(r[0]), "=r"(r[1]), "=r"(r[2]), "=r"(r[3]) : "r"(addr));
}
__device__ __forceinline__ void ldsm_x2(uint32_t* r, uint32_t addr) {
    asm volatile("ldmatrix.sync.aligned.m8n8.x2.shared.b16 {%0,%1}, [%2];"
                 : "=r"(r[0]), "=r"(r[1]) : "r"(addr));
}
__device__ __forceinline__ void mma_bf16(float* c, const uint32_t* a,
                                         const uint32_t* b) {
    asm volatile(
        "mma.sync.aligned.m16n8k16.row.col.f32.bf16.bf16.f32 "
        "{%0,%1,%2,%3}, {%4,%5,%6,%7}, {%8,%9}, {%0,%1,%2,%3};"
        : "+f"(c[0]), "+f"(c[1]), "+f"(c[2]), "+f"(c[3])
        : "r"(a[0]), "r"(a[1]), "r"(a[2]), "r"(a[3]), "r"(b[0]), "r"(b[1]));
}
__device__ __forceinline__ void cp_async16(uint32_t dst, const void* src) {
    asm volatile("cp.async.cg.shared.global [%0], [%1], 16;"
                 :: "r"(dst), "l"(src));
}
#define SW128(o) ((o) ^ (((o) >> 3) & 0x70))

__device__ __forceinline__ void pack_pair(float a, float b, uint32_t& h,
                                          uint32_t& l) {
    __nv_bfloat162 hh, ll;
    hh.x = __float2bfloat16(a);
    hh.y = __float2bfloat16(b);
    ll.x = __float2bfloat16(a - __bfloat162float(hh.x));
    ll.y = __float2bfloat16(b - __bfloat162float(hh.y));
    h = *(uint32_t*)&hh;
    l = *(uint32_t*)&ll;
}

// ---------------------------------------------------------------------------
// fp32 -> (hi, lo) bf16 split, elementwise
// ---------------------------------------------------------------------------
__global__ __launch_bounds__(256) void split_kernel(
    const float* __restrict__ x, __nv_bfloat16* __restrict__ hi,
    __nv_bfloat16* __restrict__ lo)
{
    int i = blockIdx.x * 256 + threadIdx.x;
    float4 v = ((const float4*)x)[i];
    __nv_bfloat16 h0 = __float2bfloat16(v.x), h1 = __float2bfloat16(v.y);
    __nv_bfloat16 h2 = __float2bfloat16(v.z), h3 = __float2bfloat16(v.w);
    __nv_bfloat162 a, b, c, d;
    a.x = h0; a.y = h1; b.x = h2; b.y = h3;
    c.x = __float2bfloat16(v.x - __bfloat162float(h0));
    c.y = __float2bfloat16(v.y - __bfloat162float(h1));
    d.x = __float2bfloat16(v.z - __bfloat162float(h2));
    d.y = __float2bfloat16(v.w - __bfloat162float(h3));
    ((__nv_bfloat162*)hi)[i * 2]     = a;
    ((__nv_bfloat162*)hi)[i * 2 + 1] = b;
    ((__nv_bfloat162*)lo)[i * 2]     = c;
    ((__nv_bfloat162*)lo)[i * 2 + 1] = d;
}

// ---------------------------------------------------------------------------
// W [K,N] fp32 -> W^T [N,K] split bf16
// ---------------------------------------------------------------------------
__global__ __launch_bounds__(256) void splitT_kernel(
    const float* __restrict__ W, __nv_bfloat16* __restrict__ Th,
    __nv_bfloat16* __restrict__ Tl, int K, int N)
{
    __shared__ float tile[32][33];
    int n0 = blockIdx.x * 32, k0 = blockIdx.y * 32;
    int tx = threadIdx.x & 31, ty = threadIdx.x >> 5;
#pragma unroll
    for (int j = 0; j < 4; j++) {
        int r = ty + j * 8;
        tile[r][tx] = W[(size_t)(k0 + r) * N + n0 + tx];
    }
    __syncthreads();
#pragma unroll
    for (int j = 0; j < 4; j++) {
        int r = ty + j * 8;
        float v = tile[tx][r];
        __nv_bfloat16 h = __float2bfloat16(v);
        size_t o = (size_t)(n0 + r) * K + k0 + tx;
        Th[o] = h;
        Tl[o] = __float2bfloat16(v - __bfloat162float(h));
    }
}

// ---------------------------------------------------------------------------
// mma.sync bf16-split GEMM + bias (unchanged from R9 — it works)
// ---------------------------------------------------------------------------
#define TILE_B 10240          // 128 rows * 80 bytes
#define STAGE_B (4 * TILE_B)  // Ah, Al, Bh, Bl

__global__ __launch_bounds__(256, 1) void gemm_mma_kernel(
    const __nv_bfloat16* __restrict__ Ah, const __nv_bfloat16* __restrict__ Al,
    const __nv_bfloat16* __restrict__ Bh, const __nv_bfloat16* __restrict__ Bl,
    const float* __restrict__ bias, float* __restrict__ Cm,
    int M, int N, int K)
{
    extern __shared__ __align__(128) char sm[];
    const int tid = threadIdx.x;
    const int wid = tid >> 5, lane = tid & 31;
    const int wm = wid >> 2, wn = wid & 3;
    const int bm = blockIdx.y * 128, bn = blockIdx.x * 128;
    const int NCH = K >> 5;

    float acc[4][4][4];
#pragma unroll
    for (int mt = 0; mt < 4; mt++)
#pragma unroll
        for (int nt = 0; nt < 4; nt++)
#pragma unroll
            for (int r = 0; r < 4; r++) acc[mt][nt][r] = 0.0f;

    const __nv_bfloat16* srcs[4] = {Ah, Al, Bh, Bl};

    auto load_stage = [&](int s, int k0) {
        char* base = sm + s * STAGE_B;
#pragma unroll
        for (int t = 0; t < 4; t++) {
            const __nv_bfloat16* src = srcs[t];
            int rbase = (t < 2) ? bm : bn;
#pragma unroll
            for (int j = 0; j < 2; j++) {
                int c = tid + (j << 8);
                int row = c >> 2, kc = c & 3;
                uint32_t dst = smem_u32(base + t * TILE_B + row * 80 + kc * 16);
                cp_async16(dst, src + (size_t)(rbase + row) * K + k0 + kc * 8);
            }
        }
        asm volatile("cp.async.commit_group;" ::: "memory");
    };

    load_stage(0, 0);

#pragma unroll 1
    for (int i = 0; i < NCH; i++) {
        if (i + 1 < NCH) {
            load_stage((i + 1) & 1, (i + 1) << 5);
            asm volatile("cp.async.wait_group 1;" ::: "memory");
        } else {
            asm volatile("cp.async.wait_group 0;" ::: "memory");
        }
        __syncthreads();

        char* base = sm + (i & 1) * STAGE_B;
        uint32_t aAh = smem_u32(base);
        uint32_t aAl = aAh + TILE_B;
        uint32_t aBh = aAh + 2 * TILE_B;
        uint32_t aBl = aAh + 3 * TILE_B;

#pragma unroll
        for (int ks = 0; ks < 2; ks++) {
            uint32_t ah[4][4], al[4][4], bh[4][2], bl[4][2];
            int arow = wm * 64 + (lane & 15);
            int acol = ks * 32 + ((lane >> 4) << 4);
            int brow = wn * 32 + (lane & 7);
            int bcol = ks * 32 + (((lane >> 3) & 1) << 4);
#pragma unroll
            for (int mt = 0; mt < 4; mt++) {
                uint32_t off = (uint32_t)(arow + mt * 16) * 80 + acol;
                ldsm_x4(ah[mt], aAh + off);
                ldsm_x4(al[mt], aAl + off);
            }
#pragma unroll
            for (int nt = 0; nt < 4; nt++) {
                uint32_t off = (uint32_t)(brow + nt * 8) * 80 + bcol;
                ldsm_x2(bh[nt], aBh + off);
                ldsm_x2(bl[nt], aBl + off);
            }
#pragma unroll
            for (int mt = 0; mt < 4; mt++)
#pragma unroll
                for (int nt = 0; nt < 4; nt++) {
                    mma_bf16(acc[mt][nt], ah[mt], bh[nt]);
                    mma_bf16(acc[mt][nt], ah[mt], bl[nt]);
                    mma_bf16(acc[mt][nt], al[mt], bh[nt]);
                }
        }
        __syncthreads();
    }

    int gq = lane >> 2, tr = lane & 3;
#pragma unroll
    for (int mt = 0; mt < 4; mt++) {
        int r0 = bm + wm * 64 + mt * 16 + gq;
#pragma unroll
        for (int nt = 0; nt < 4; nt++) {
            int col = bn + wn * 32 + nt * 8 + tr * 2;
            float bx = bias[col], by = bias[col + 1];
            float2 v0 = {acc[mt][nt][0] + bx, acc[mt][nt][1] + by};
            float2 v1 = {acc[mt][nt][2] + bx, acc[mt][nt][3] + by};
            *(float2*)(Cm + (size_t)r0 * N + col)       = v0;
            *(float2*)(Cm + (size_t)(r0 + 8) * N + col) = v1;
        }
    }
}

// ---------------------------------------------------------------------------
// RMSNorm + rotary + scatter, emitting split bf16 Q/K/V
// ---------------------------------------------------------------------------
__device__ __forceinline__ void store_split(__nv_bfloat16* h, __nv_bfloat16* l,
                                            size_t i, float v) {
    __nv_bfloat16 hh = __float2bfloat16(v);
    h[i] = hh;
    l[i] = __float2bfloat16(v - __bfloat162float(hh));
}

__global__ __launch_bounds__(256) void rmsrot_kernel(
    const float* __restrict__ qkv, const float* __restrict__ cosT,
    const float* __restrict__ sinT,
    __nv_bfloat16* __restrict__ Qh, __nv_bfloat16* __restrict__ Ql,
    __nv_bfloat16* __restrict__ Kh, __nv_bfloat16* __restrict__ Kl,
    __nv_bfloat16* __restrict__ Vh, __nv_bfloat16* __restrict__ Vl)
{
    int lane = threadIdx.x & 31;
    int row  = blockIdx.x * 8 + (threadIdx.x >> 5);
    int h = row & (H_ - 1);
    int t = (row >> 4) & (T_ - 1);
    int b = row >> 15;

    const float* src = qkv + (size_t)(b * T_ + t) * (3 * C_) + h * D_;
    float q0 = src[lane],        q1 = src[lane + 32];
    float k0 = src[C_ + lane],   k1 = src[C_ + lane + 32];
    float v0 = src[2*C_ + lane], v1 = src[2*C_ + lane + 32];

    float sq = q0 * q0 + q1 * q1;
    float sk = k0 * k0 + k1 * k1;
#pragma unroll
    for (int off = 16; off; off >>= 1) {
        sq += __shfl_xor_sync(0xffffffffu, sq, off);
        sk += __shfl_xor_sync(0xffffffffu, sk, off);
    }
    float rq = rsqrtf(sq * (1.0f / 64.0f) + EPSF);
    float rk = rsqrtf(sk * (1.0f / 64.0f) + EPSF);
    q0 *= rq; q1 *= rq; k0 *= rk; k1 *= rk;

    float c0 = cosT[t * D_ + lane], c1 = cosT[t * D_ + lane + 32];
    float s0 = sinT[t * D_ + lane], s1 = sinT[t * D_ + lane + 32];

    float qo0 = q0 * c0 - q1 * s0;
    float qo1 = q1 * c1 + q0 * s1;
    float ko0 = k0 * c0 - k1 * s0;
    float ko1 = k1 * c1 + k0 * s1;

    size_t dst = ((size_t)(b * H_ + h) * T_ + t) * D_;
    store_split(Qh, Ql, dst + lane,      qo0);
    store_split(Qh, Ql, dst + lane + 32, qo1);
    store_split(Kh, Kl, dst + lane,      ko0);
    store_split(Kh, Kl, dst + lane + 32, ko1);
    store_split(Vh, Vl, dst + lane,      v0);
    store_split(Vh, Vl, dst + lane + 32, v1);
}

// ---------------------------------------------------------------------------
// Causal flash attention via mma.sync, bf16 3-term split, fp32 softmax.
// 128 q-rows per CTA, 8 warps x 16 rows; KV tiles of 64, double-buffered.
// Smem (bytes): QH 0, QL 16384; stage s at 32768+s*32768:
//   KH +0, KL +8192, VH +16384, VL +24576.   Total 98304.
// All tiles SW128-swizzled, 128-byte rows (64 bf16 = full head dim).
// ---------------------------------------------------------------------------
__global__ __launch_bounds__(256, 1) void attn_mma_kernel(
    const __nv_bfloat16* __restrict__ Qh, const __nv_bfloat16* __restrict__ Ql,
    const __nv_bfloat16* __restrict__ Kh, const __nv_bfloat16* __restrict__ Kl,
    const __nv_bfloat16* __restrict__ Vh, const __nv_bfloat16* __restrict__ Vl,
    __nv_bfloat16* __restrict__ Oh, __nv_bfloat16* __restrict__ Ol)
{
    extern __shared__ __align__(128) char sm[];
    uint32_t smb = smem_u32(sm);
    const int tid = threadIdx.x, wid = tid >> 5, lane = tid & 31;
    const int g = lane >> 2, tr = lane & 3;
    const int i0 = (int)(gridDim.x - 1 - blockIdx.x) * 128;  // heavy blocks first
    const int bh = blockIdx.y;
    const size_t base = (size_t)bh * T_ * D_;

    // ---- load Q tile (hi+lo): 128 rows x 128 bytes = 1024 16B chunks -------
#pragma unroll
    for (int j = 0; j < 4; j++) {
        int c = tid + (j << 8);          // 0..1023
        int r = c >> 3, ck = c & 7;
        uint32_t off = SW128((uint32_t)(r * 128 + ck * 16));
        size_t go = base + (size_t)(i0 + r) * D_ + ck * 8;
        cp_async16(smb + off,         Qh + go);
        cp_async16(smb + 16384 + off, Ql + go);
    }
    asm volatile("cp.async.commit_group;" ::: "memory");

    // ---- stage loader: each sub-tile = 64 rows x 128B = 512 16B chunks -----
    auto load_kv = [&](int s, int j0) {
        uint32_t sb = smb + 32768 + (uint32_t)s * 32768u;
#pragma unroll
        for (int j = 0; j < 2; j++) {
            int c = tid + (j << 8);      // 0..511
            int r = c >> 3, ck = c & 7;
            uint32_t off = SW128((uint32_t)(r * 128 + ck * 16));
            size_t go = base + (size_t)(j0 + r) * D_ + ck * 8;
            cp_async16(sb + off,         Kh + go);
            cp_async16(sb + 8192 + off,  Kl + go);
            cp_async16(sb + 16384 + off, Vh + go);
            cp_async16(sb + 24576 + off, Vl + go);
        }
        asm volatile("cp.async.commit_group;" ::: "memory");
    };

    load_kv(0, 0);
    asm volatile("cp.async.wait_group 0;" ::: "memory");
    __syncthreads();

    // ---- Q fragments into registers (constant over kv loop) ----------------
    uint32_t qfh[4][4], qfl[4][4];
    {
        int arow = wid * 16 + (lane & 15);
        int acolb = ((lane >> 4) & 1) * 16;
#pragma unroll
        for (int kb = 0; kb < 4; kb++) {
            uint32_t off = SW128((uint32_t)(arow * 128 + kb * 32 + acolb));
            ldsm_x4(qfh[kb], smb + off);
            ldsm_x4(qfl[kb], smb + 16384 + off);
        }
    }

    float o[8][4];
#pragma unroll
    for (int dt = 0; dt < 8; dt++)
#pragma unroll
        for (int e = 0; e < 4; e++) o[dt][e] = 0.0f;
    float m0 = -1e30f, m1 = -1e30f, l0 = 0.0f, l1 = 0.0f;

    const int gr0 = i0 + wid * 16 + g;
    const int gr1 = gr0 + 8;
    const int wrow_max = i0 + wid * 16 + 15;
    const int NT = i0 / 64 + 2;

#pragma unroll 1
    for (int jt = 0; jt < NT; jt++) {
        int j0 = jt * 64;
        if (jt + 1 < NT) {
            load_kv((jt + 1) & 1, (jt + 1) * 64);
            asm volatile("cp.async.wait_group 1;" ::: "memory");
        } else {
            asm volatile("cp.async.wait_group 0;" ::: "memory");
        }
        __syncthreads();

        if (j0 <= wrow_max) {   // warp has at least one unmasked element
            uint32_t kh_b = smb + 32768 + (uint32_t)(jt & 1) * 32768u;
            uint32_t kl_b = kh_b + 8192;
            uint32_t vh_b = kh_b + 16384;
            uint32_t vl_b = kh_b + 24576;

            // ---- S = scale * Q K^T (3-term split) ---------------------------
            float s[8][4];
#pragma unroll
            for (int nt = 0; nt < 8; nt++)
#pragma unroll
                for (int e = 0; e < 4; e++) s[nt][e] = 0.0f;

#pragma unroll
            for (int kb = 0; kb < 4; kb++) {
                int krow = ((lane >> 4) & 1) * 8 + (lane & 7);
                int kcol = kb * 32 + ((lane >> 3) & 1) * 16;
#pragma unroll
                for (int ntp = 0; ntp < 4; ntp++) {
                    uint32_t off = SW128((uint32_t)((ntp * 16 + krow) * 128 + kcol));
                    uint32_t th[4], tl[4];
                    ldsm_x4(th, kh_b + off);
                    ldsm_x4(tl, kl_b + off);
                    mma_bf16(s[2*ntp],     qfh[kb], th);
                    mma_bf16(s[2*ntp],     qfh[kb], tl);
                    mma_bf16(s[2*ntp],     qfl[kb], th);
                    mma_bf16(s[2*ntp + 1], qfh[kb], th + 2);
                    mma_bf16(s[2*ntp + 1], qfh[kb], tl + 2);
                    mma_bf16(s[2*ntp + 1], qfl[kb], th + 2);
                }
            }

            // ---- scale + causal mask ---------------------------------------
#pragma unroll
            for (int nt = 0; nt < 8; nt++)
#pragma unroll
                for (int e = 0; e < 4; e++) s[nt][e] *= 0.125f;

            if (j0 + 63 > i0 + wid * 16) {
#pragma unroll
                for (int nt = 0; nt < 8; nt++) {
                    int c = j0 + nt * 8 + tr * 2;
                    if (c > gr0)     s[nt][0] = -1e30f;
                    if (c + 1 > gr0) s[nt][1] = -1e30f;
                    if (c > gr1)     s[nt][2] = -1e30f;
                    if (c + 1 > gr1) s[nt][3] = -1e30f;
                }
            }

            // ---- online softmax --------------------------------------------
            float mx0 = -1e30f, mx1 = -1e30f;
#pragma unroll
            for (int nt = 0; nt < 8; nt++) {
                mx0 = fmaxf(mx0, fmaxf(s[nt][0], s[nt][1]));
                mx1 = fmaxf(mx1, fmaxf(s[nt][2], s[nt][3]));
            }
            mx0 = fmaxf(mx0, __shfl_xor_sync(0xffffffffu, mx0, 1));
            mx0 = fmaxf(mx0, __shfl_xor_sync(0xffffffffu, mx0, 2));
            mx1 = fmaxf(mx1, __shfl_xor_sync(0xffffffffu, mx1, 1));
            mx1 = fmaxf(mx1, __shfl_xor_sync(0xffffffffu, mx1, 2));

            float mn0 = fmaxf(m0, mx0), mn1 = fmaxf(m1, mx1);
            float al0 = __expf(m0 - mn0), al1 = __expf(m1 - mn1);
            m0 = mn0; m1 = mn1;

            float sum0 = 0.0f, sum1 = 0.0f;
#pragma unroll
            for (int nt = 0; nt < 8; nt++) {
                s[nt][0] = __expf(s[nt][0] - mn0); sum0 += s[nt][0];
                s[nt][1] = __expf(s[nt][1] - mn0); sum0 += s[nt][1];
                s[nt][2] = __expf(s[nt][2] - mn1); sum1 += s[nt][2];
                s[nt][3] = __expf(s[nt][3] - mn1); sum1 += s[nt][3];
            }
            sum0 += __shfl_xor_sync(0xffffffffu, sum0, 1);
            sum0 += __shfl_xor_sync(0xffffffffu, sum0, 2);
            sum1 += __shfl_xor_sync(0xffffffffu, sum1, 1);
            sum1 += __shfl_xor_sync(0xffffffffu, sum1, 2);
            l0 = l0 * al0 + sum0;
            l1 = l1 * al1 + sum1;
#pragma unroll
            for (int dt = 0; dt < 8; dt++) {
                o[dt][0] *= al0; o[dt][1] *= al0;
                o[dt][2] *= al1; o[dt][3] *= al1;
            }

            // ---- O += P V (3-term split, P packed in-register) -------------
#pragma unroll
            for (int kb = 0; kb < 4; kb++) {
                uint32_t pah[4], pal[4];
                pack_pair(s[2*kb][0],     s[2*kb][1],     pah[0], pal[0]);
                pack_pair(s[2*kb][2],     s[2*kb][3],     pah[1], pal[1]);
                pack_pair(s[2*kb + 1][0], s[2*kb + 1][1], pah[2], pal[2]);
                pack_pair(s[2*kb + 1][2], s[2*kb + 1][3], pah[3], pal[3]);

                int vrow = kb * 16 + ((lane >> 3) & 1) * 8 + (lane & 7);
                int vcolb = ((lane >> 4) & 1) * 16;
#pragma unroll
                for (int dtp = 0; dtp < 4; dtp++) {
                    uint32_t off = SW128((uint32_t)(vrow * 128 + dtp * 32 + vcolb));
                    uint32_t th[4], tl[4];
                    ldsm_x4_t(th, vh_b + off);
                    ldsm_x4_t(tl, vl_b + off);
                    mma_bf16(o[2*dtp],     pah, th);
                    mma_bf16(o[2*dtp],     pal, th);
                    mma_bf16(o[2*dtp],     pah, tl);
                    mma_bf16(o[2*dtp + 1], pah, th + 2);
                    mma_bf16(o[2*dtp + 1], pal, th + 2);
                    mma_bf16(o[2*dtp + 1], pah, tl + 2);
                }
            }
        }
        __syncthreads();   // all reads of this stage done before overwrite
    }

    // ---- epilogue: normalize, split to bf16 hi/lo, write [b,t,h*64+d] ------
    float inv0 = 1.0f / l0, inv1 = 1.0f / l1;
    int b = bh >> 4, h = bh & 15;
#pragma unroll
    for (int dt = 0; dt < 8; dt++) {
        int col = h * 64 + dt * 8 + tr * 2;
        float y00 = o[dt][0] * inv0, y01 = o[dt][1] * inv0;
        float y10 = o[dt][2] * inv1, y11 = o[dt][3] * inv1;
        uint32_t h0, lo0, h1, lo1;
        pack_pair(y00, y01, h0, lo0);
        pack_pair(y10, y11, h1, lo1);
        size_t o0 = (size_t)(b * T_ + gr0) * C_ + col;
        size_t o1 = (size_t)(b * T_ + gr1) * C_ + col;
        *(uint32_t*)(Oh + o0) = h0;
        *(uint32_t*)(Ol + o0) = lo0;
        *(uint32_t*)(Oh + o1) = h1;
        *(uint32_t*)(Ol + o1) = lo1;
    }
}

// ---------------------------------------------------------------------------

extern "C" void kernel_launch(void* const* d_in, const int* in_sizes, int n_in,
                              void* d_out, int out_size)
{
    const float* x      = (const float*)d_in[0];
    const float* cosT   = (const float*)d_in[1];
    const float* sinT   = (const float*)d_in[2];
    const float* W_attn = (const float*)d_in[3];
    const float* b_attn = (const float*)d_in[4];
    const float* W_proj = (const float*)d_in[5];
    const float* b_proj = (const float*)d_in[6];
    float* out = (float*)d_out;

    float* qkv;
    __nv_bfloat16 *xh, *xl, *wah, *wal, *wph, *wpl, *ath, *atl;
    __nv_bfloat16 *qh, *ql, *kh, *kl, *vh, *vl;
    cudaGetSymbolAddress((void**)&qkv, g_qkv);
    cudaGetSymbolAddress((void**)&xh,  g_xh);
    cudaGetSymbolAddress((void**)&xl,  g_xl);
    cudaGetSymbolAddress((void**)&wah, g_wah);
    cudaGetSymbolAddress((void**)&wal, g_wal);
    cudaGetSymbolAddress((void**)&wph, g_wph);
    cudaGetSymbolAddress((void**)&wpl, g_wpl);
    cudaGetSymbolAddress((void**)&ath, g_ath);
    cudaGetSymbolAddress((void**)&atl, g_atl);
    cudaGetSymbolAddress((void**)&qh,  g_qh);
    cudaGetSymbolAddress((void**)&ql,  g_ql);
    cudaGetSymbolAddress((void**)&kh,  g_kh);
    cudaGetSymbolAddress((void**)&kl,  g_kl);
    cudaGetSymbolAddress((void**)&vh,  g_vh);
    cudaGetSymbolAddress((void**)&vl,  g_vl);

    const int GEMM_SMEM = 2 * STAGE_B;  // 81920
    cudaFuncSetAttribute(gemm_mma_kernel,
                         cudaFuncAttributeMaxDynamicSharedMemorySize, GEMM_SMEM);
    const int ATTN_SMEM = 98304;
    cudaFuncSetAttribute(attn_mma_kernel,
                         cudaFuncAttributeMaxDynamicSharedMemorySize, ATTN_SMEM);

    // 0) splits
    split_kernel<<<BT_ * C_ / 1024, 256>>>(x, xh, xl);
    splitT_kernel<<<dim3(3 * C_ / 32, C_ / 32), 256>>>(W_attn, wah, wal, C_, 3 * C_);
    splitT_kernel<<<dim3(C_ / 32, C_ / 32), 256>>>(W_proj, wph, wpl, C_, C_);

    // 1) QKV GEMM (tensor cores)
    gemm_mma_kernel<<<dim3(3 * C_ / 128, BT_ / 128), 256, GEMM_SMEM>>>(
        xh, xl, wah, wal, b_attn, qkv, BT_, 3 * C_, C_);

    // 2) RMSNorm + rotary + scatter to split bf16 Q/K/V
    rmsrot_kernel<<<(B_ * T_ * H_) / 8, 256>>>(qkv, cosT, sinT,
                                               qh, ql, kh, kl, vh, vl);

    // 3) Causal flash attention (tensor cores, split bf16)
    attn_mma_kernel<<<dim3(T_ / 128, B_ * H_), 256, ATTN_SMEM>>>(
        qh, ql, kh, kl, vh, vl, ath, atl);

    // 4) proj GEMM (tensor cores)
    gemm_mma_kernel<<<dim3(C_ / 128, BT_ / 128), 256, GEMM_SMEM>>>(
        ath, atl, wph, wpl, b_proj, out, BT_, C_, C_);
}

// round 15
// speedup vs baseline: 2.7899x; 1.1316x over previous
#include <cuda_runtime.h>
#include <cuda_bf16.h>
#include <cstdint>
#include <math.h>

#define B_ 2
#define T_ 2048
#define C_ 1024
#define H_ 16
#define D_ 64
#define BT_ (B_*T_)
#define EPSF 1.1920929e-07f

// ---------------- scratch (device globals; no allocs allowed) ---------------
__device__ float g_qkv[(size_t)BT_*3*C_];          // [4096, 3072]

__device__ __nv_bfloat16 g_xh[(size_t)BT_*C_];     // x split
__device__ __nv_bfloat16 g_xl[(size_t)BT_*C_];
__device__ __nv_bfloat16 g_wah[(size_t)3*C_*C_];   // W_attn^T split  [3072,1024]
__device__ __nv_bfloat16 g_wal[(size_t)3*C_*C_];
__device__ __nv_bfloat16 g_wph[(size_t)C_*C_];     // W_proj^T split  [1024,1024]
__device__ __nv_bfloat16 g_wpl[(size_t)C_*C_];

__device__ __nv_bfloat16 g_qh[(size_t)B_*H_*T_*D_];  // Q/K/V split [B,H,T,D]
__device__ __nv_bfloat16 g_ql[(size_t)B_*H_*T_*D_];
__device__ __nv_bfloat16 g_kh[(size_t)B_*H_*T_*D_];
__device__ __nv_bfloat16 g_kl[(size_t)B_*H_*T_*D_];
__device__ __nv_bfloat16 g_vh[(size_t)B_*H_*T_*D_];
__device__ __nv_bfloat16 g_vl[(size_t)B_*H_*T_*D_];

__device__ __nv_bfloat16 g_ath[(size_t)BT_*C_];    // attention out split [4096,1024]
__device__ __nv_bfloat16 g_atl[(size_t)BT_*C_];

// ---------------------------- helpers ---------------------------------------
__device__ __forceinline__ uint32_t smem_u32(const void* p) {
    uint32_t a;
    asm("{ .reg .u64 t; cvta.to.shared.u64 t, %1; cvt.u32.u64 %0, t; }"
        : "=r"(a) : "l"(p));
    return a;
}
__device__ __forceinline__ void ldsm_x4(uint32_t* r, uint32_t addr) {
    asm volatile("ldmatrix.sync.aligned.m8n8.x4.shared.b16 {%0,%1,%2,%3}, [%4];"
                 : "=r"(r[0]), "=r"(r[1]), "=r"(r[2]), "=r"(r[3]) : "r"(addr));
}
__device__ __forceinline__ void ldsm_x4_t(uint32_t* r, uint32_t addr) {
    asm volatile("ldmatrix.sync.aligned.m8n8.x4.trans.shared.b16 {%0,%1,%2,%3}, [%4];"
                 : "=r"(r[0]), "=r"(r[1]), "=r"(r[2]), "=r"(r[3]) : "r"(addr));
}
__device__ __forceinline__ void ldsm_x2(uint32_t* r, uint32_t addr) {
    asm volatile("ldmatrix.sync.aligned.m8n8.x2.shared.b16 {%0,%1}, [%2];"
                 : "=r"(r[0]), "=r"(r[1]) : "r"(addr));
}
__device__ __forceinline__ void mma_bf16(float* c, const uint32_t* a,
                                         const uint32_t* b) {
    asm volatile(
        "mma.sync.aligned.m16n8k16.row.col.f32.bf16.bf16.f32 "
        "{%0,%1,%2,%3}, {%4,%5,%6,%7}, {%8,%9}, {%0,%1,%2,%3};"
        : "+f"(c[0]), "+f"(c[1]), "+f"(c[2]), "+f"(c[3])
        : "r"(a[0]), "r"(a[1]), "r"(a[2]), "r"(a[3]), "r"(b[0]), "r"(b[1]));
}
__device__ __forceinline__ void cp_async16(uint32_t dst, const void* src) {
    asm volatile("cp.async.cg.shared.global [%0], [%1], 16;"
                 :: "r"(dst), "l"(src));
}
#define SW128(o) ((o) ^ (((o) >> 3) & 0x70))

__device__ __forceinline__ void pack_pair(float a, float b, uint32_t& h,
                                          uint32_t& l) {
    __nv_bfloat162 hh, ll;
    hh.x = __float2bfloat16(a);
    hh.y = __float2bfloat16(b);
    ll.x = __float2bfloat16(a - __bfloat162float(hh.x));
    ll.y = __float2bfloat16(b - __bfloat162float(hh.y));
    h = *(uint32_t*)&hh;
    l = *(uint32_t*)&ll;
}

// ---------------------------------------------------------------------------
// fp32 -> (hi, lo) bf16 split, elementwise
// ---------------------------------------------------------------------------
__global__ __launch_bounds__(256) void split_kernel(
    const float* __restrict__ x, __nv_bfloat16* __restrict__ hi,
    __nv_bfloat16* __restrict__ lo)
{
    int i = blockIdx.x * 256 + threadIdx.x;
    float4 v = ((const float4*)x)[i];
    __nv_bfloat16 h0 = __float2bfloat16(v.x), h1 = __float2bfloat16(v.y);
    __nv_bfloat16 h2 = __float2bfloat16(v.z), h3 = __float2bfloat16(v.w);
    __nv_bfloat162 a, b, c, d;
    a.x = h0; a.y = h1; b.x = h2; b.y = h3;
    c.x = __float2bfloat16(v.x - __bfloat162float(h0));
    c.y = __float2bfloat16(v.y - __bfloat162float(h1));
    d.x = __float2bfloat16(v.z - __bfloat162float(h2));
    d.y = __float2bfloat16(v.w - __bfloat162float(h3));
    ((__nv_bfloat162*)hi)[i * 2]     = a;
    ((__nv_bfloat162*)hi)[i * 2 + 1] = b;
    ((__nv_bfloat162*)lo)[i * 2]     = c;
    ((__nv_bfloat162*)lo)[i * 2 + 1] = d;
}

// ---------------------------------------------------------------------------
// W [K,N] fp32 -> W^T [N,K] split bf16
// ---------------------------------------------------------------------------
__global__ __launch_bounds__(256) void splitT_kernel(
    const float* __restrict__ W, __nv_bfloat16* __restrict__ Th,
    __nv_bfloat16* __restrict__ Tl, int K, int N)
{
    __shared__ float tile[32][33];
    int n0 = blockIdx.x * 32, k0 = blockIdx.y * 32;
    int tx = threadIdx.x & 31, ty = threadIdx.x >> 5;
#pragma unroll
    for (int j = 0; j < 4; j++) {
        int r = ty + j * 8;
        tile[r][tx] = W[(size_t)(k0 + r) * N + n0 + tx];
    }
    __syncthreads();
#pragma unroll
    for (int j = 0; j < 4; j++) {
        int r = ty + j * 8;
        float v = tile[tx][r];
        __nv_bfloat16 h = __float2bfloat16(v);
        size_t o = (size_t)(n0 + r) * K + k0 + tx;
        Th[o] = h;
        Tl[o] = __float2bfloat16(v - __bfloat162float(h));
    }
}

// ---------------------------------------------------------------------------
// mma.sync bf16-split GEMM + bias: restructured for 2 CTAs/SM.
//   - __launch_bounds__(256, 2) caps regs at 128.
//   - B fragments (16 regs) loaded once per ks; A fragments streamed per
//     mt-tile (8 live regs) so acc(64)+B(16)+A(8)+addr fits the cap.
// ---------------------------------------------------------------------------
#define TILE_B 10240          // 128 rows * 80 bytes
#define STAGE_B (4 * TILE_B)  // Ah, Al, Bh, Bl

__global__ __launch_bounds__(256, 2) void gemm_mma_kernel(
    const __nv_bfloat16* __restrict__ Ah, const __nv_bfloat16* __restrict__ Al,
    const __nv_bfloat16* __restrict__ Bh, const __nv_bfloat16* __restrict__ Bl,
    const float* __restrict__ bias, float* __restrict__ Cm,
    int M, int N, int K)
{
    extern __shared__ __align__(128) char sm[];
    const int tid = threadIdx.x;
    const int wid = tid >> 5, lane = tid & 31;
    const int wm = wid >> 2, wn = wid & 3;
    const int bm = blockIdx.y * 128, bn = blockIdx.x * 128;
    const int NCH = K >> 5;

    float acc[4][4][4];
#pragma unroll
    for (int mt = 0; mt < 4; mt++)
#pragma unroll
        for (int nt = 0; nt < 4; nt++)
#pragma unroll
            for (int r = 0; r < 4; r++) acc[mt][nt][r] = 0.0f;

    const __nv_bfloat16* srcs[4] = {Ah, Al, Bh, Bl};

    auto load_stage = [&](int s, int k0) {
        char* base = sm + s * STAGE_B;
#pragma unroll
        for (int t = 0; t < 4; t++) {
            const __nv_bfloat16* src = srcs[t];
            int rbase = (t < 2) ? bm : bn;
#pragma unroll
            for (int j = 0; j < 2; j++) {
                int c = tid + (j << 8);
                int row = c >> 2, kc = c & 3;
                uint32_t dst = smem_u32(base + t * TILE_B + row * 80 + kc * 16);
                cp_async16(dst, src + (size_t)(rbase + row) * K + k0 + kc * 8);
            }
        }
        asm volatile("cp.async.commit_group;" ::: "memory");
    };

    load_stage(0, 0);

#pragma unroll 1
    for (int i = 0; i < NCH; i++) {
        if (i + 1 < NCH) {
            load_stage((i + 1) & 1, (i + 1) << 5);
            asm volatile("cp.async.wait_group 1;" ::: "memory");
        } else {
            asm volatile("cp.async.wait_group 0;" ::: "memory");
        }
        __syncthreads();

        char* base = sm + (i & 1) * STAGE_B;
        uint32_t aAh = smem_u32(base);
        uint32_t aAl = aAh + TILE_B;
        uint32_t aBh = aAh + 2 * TILE_B;
        uint32_t aBl = aAh + 3 * TILE_B;

#pragma unroll
        for (int ks = 0; ks < 2; ks++) {
            // B fragments: resident for whole ks step (16 regs)
            uint32_t bh[4][2], bl[4][2];
            int brow = wn * 32 + (lane & 7);
            int bcol = ks * 32 + (((lane >> 3) & 1) << 4);
#pragma unroll
            for (int nt = 0; nt < 4; nt++) {
                uint32_t off = (uint32_t)(brow + nt * 8) * 80 + bcol;
                ldsm_x2(bh[nt], aBh + off);
                ldsm_x2(bl[nt], aBl + off);
            }
            // A fragments: streamed per mt tile (8 live regs)
            int arow = wm * 64 + (lane & 15);
            int acol = ks * 32 + ((lane >> 4) << 4);
#pragma unroll
            for (int mt = 0; mt < 4; mt++) {
                uint32_t ah[4], al[4];
                uint32_t off = (uint32_t)(arow + mt * 16) * 80 + acol;
                ldsm_x4(ah, aAh + off);
                ldsm_x4(al, aAl + off);
#pragma unroll
                for (int nt = 0; nt < 4; nt++) {
                    mma_bf16(acc[mt][nt], ah, bh[nt]);
                    mma_bf16(acc[mt][nt], ah, bl[nt]);
                    mma_bf16(acc[mt][nt], al, bh[nt]);
                }
            }
        }
        __syncthreads();
    }

    int gq = lane >> 2, tr = lane & 3;
#pragma unroll
    for (int mt = 0; mt < 4; mt++) {
        int r0 = bm + wm * 64 + mt * 16 + gq;
#pragma unroll
        for (int nt = 0; nt < 4; nt++) {
            int col = bn + wn * 32 + nt * 8 + tr * 2;
            float bx = bias[col], by = bias[col + 1];
            float2 v0 = {acc[mt][nt][0] + bx, acc[mt][nt][1] + by};
            float2 v1 = {acc[mt][nt][2] + bx, acc[mt][nt][3] + by};
            *(float2*)(Cm + (size_t)r0 * N + col)       = v0;
            *(float2*)(Cm + (size_t)(r0 + 8) * N + col) = v1;
        }
    }
}

// ---------------------------------------------------------------------------
// RMSNorm + rotary + scatter, emitting split bf16 Q/K/V
// ---------------------------------------------------------------------------
__device__ __forceinline__ void store_split(__nv_bfloat16* h, __nv_bfloat16* l,
                                            size_t i, float v) {
    __nv_bfloat16 hh = __float2bfloat16(v);
    h[i] = hh;
    l[i] = __float2bfloat16(v - __bfloat162float(hh));
}

__global__ __launch_bounds__(256) void rmsrot_kernel(
    const float* __restrict__ qkv, const float* __restrict__ cosT,
    const float* __restrict__ sinT,
    __nv_bfloat16* __restrict__ Qh, __nv_bfloat16* __restrict__ Ql,
    __nv_bfloat16* __restrict__ Kh, __nv_bfloat16* __restrict__ Kl,
    __nv_bfloat16* __restrict__ Vh, __nv_bfloat16* __restrict__ Vl)
{
    int lane = threadIdx.x & 31;
    int row  = blockIdx.x * 8 + (threadIdx.x >> 5);
    int h = row & (H_ - 1);
    int t = (row >> 4) & (T_ - 1);
    int b = row >> 15;

    const float* src = qkv + (size_t)(b * T_ + t) * (3 * C_) + h * D_;
    float q0 = src[lane],        q1 = src[lane + 32];
    float k0 = src[C_ + lane],   k1 = src[C_ + lane + 32];
    float v0 = src[2*C_ + lane], v1 = src[2*C_ + lane + 32];

    float sq = q0 * q0 + q1 * q1;
    float sk = k0 * k0 + k1 * k1;
#pragma unroll
    for (int off = 16; off; off >>= 1) {
        sq += __shfl_xor_sync(0xffffffffu, sq, off);
        sk += __shfl_xor_sync(0xffffffffu, sk, off);
    }
    float rq = rsqrtf(sq * (1.0f / 64.0f) + EPSF);
    float rk = rsqrtf(sk * (1.0f / 64.0f) + EPSF);
    q0 *= rq; q1 *= rq; k0 *= rk; k1 *= rk;

    float c0 = cosT[t * D_ + lane], c1 = cosT[t * D_ + lane + 32];
    float s0 = sinT[t * D_ + lane], s1 = sinT[t * D_ + lane + 32];

    float qo0 = q0 * c0 - q1 * s0;
    float qo1 = q1 * c1 + q0 * s1;
    float ko0 = k0 * c0 - k1 * s0;
    float ko1 = k1 * c1 + k0 * s1;

    size_t dst = ((size_t)(b * H_ + h) * T_ + t) * D_;
    store_split(Qh, Ql, dst + lane,      qo0);
    store_split(Qh, Ql, dst + lane + 32, qo1);
    store_split(Kh, Kl, dst + lane,      ko0);
    store_split(Kh, Kl, dst + lane + 32, ko1);
    store_split(Vh, Vl, dst + lane,      v0);
    store_split(Vh, Vl, dst + lane + 32, v1);
}

// ---------------------------------------------------------------------------
// Causal flash attention via mma.sync, bf16 3-term split, fp32 softmax.
// (unchanged from R13 — it works)
// ---------------------------------------------------------------------------
__global__ __launch_bounds__(256, 1) void attn_mma_kernel(
    const __nv_bfloat16* __restrict__ Qh, const __nv_bfloat16* __restrict__ Ql,
    const __nv_bfloat16* __restrict__ Kh, const __nv_bfloat16* __restrict__ Kl,
    const __nv_bfloat16* __restrict__ Vh, const __nv_bfloat16* __restrict__ Vl,
    __nv_bfloat16* __restrict__ Oh, __nv_bfloat16* __restrict__ Ol)
{
    extern __shared__ __align__(128) char sm[];
    uint32_t smb = smem_u32(sm);
    const int tid = threadIdx.x, wid = tid >> 5, lane = tid & 31;
    const int g = lane >> 2, tr = lane & 3;
    const int i0 = (int)(gridDim.x - 1 - blockIdx.x) * 128;  // heavy blocks first
    const int bh = blockIdx.y;
    const size_t base = (size_t)bh * T_ * D_;

#pragma unroll
    for (int j = 0; j < 4; j++) {
        int c = tid + (j << 8);          // 0..1023
        int r = c >> 3, ck = c & 7;
        uint32_t off = SW128((uint32_t)(r * 128 + ck * 16));
        size_t go = base + (size_t)(i0 + r) * D_ + ck * 8;
        cp_async16(smb + off,         Qh + go);
        cp_async16(smb + 16384 + off, Ql + go);
    }
    asm volatile("cp.async.commit_group;" ::: "memory");

    auto load_kv = [&](int s, int j0) {
        uint32_t sb = smb + 32768 + (uint32_t)s * 32768u;
#pragma unroll
        for (int j = 0; j < 2; j++) {
            int c = tid + (j << 8);      // 0..511
            int r = c >> 3, ck = c & 7;
            uint32_t off = SW128((uint32_t)(r * 128 + ck * 16));
            size_t go = base + (size_t)(j0 + r) * D_ + ck * 8;
            cp_async16(sb + off,         Kh + go);
            cp_async16(sb + 8192 + off,  Kl + go);
            cp_async16(sb + 16384 + off, Vh + go);
            cp_async16(sb + 24576 + off, Vl + go);
        }
        asm volatile("cp.async.commit_group;" ::: "memory");
    };

    load_kv(0, 0);
    asm volatile("cp.async.wait_group 0;" ::: "memory");
    __syncthreads();

    uint32_t qfh[4][4], qfl[4][4];
    {
        int arow = wid * 16 + (lane & 15);
        int acolb = ((lane >> 4) & 1) * 16;
#pragma unroll
        for (int kb = 0; kb < 4; kb++) {
            uint32_t off = SW128((uint32_t)(arow * 128 + kb * 32 + acolb));
            ldsm_x4(qfh[kb], smb + off);
            ldsm_x4(qfl[kb], smb + 16384 + off);
        }
    }

    float o[8][4];
#pragma unroll
    for (int dt = 0; dt < 8; dt++)
#pragma unroll
        for (int e = 0; e < 4; e++) o[dt][e] = 0.0f;
    float m0 = -1e30f, m1 = -1e30f, l0 = 0.0f, l1 = 0.0f;

    const int gr0 = i0 + wid * 16 + g;
    const int gr1 = gr0 + 8;
    const int wrow_max = i0 + wid * 16 + 15;
    const int NT = i0 / 64 + 2;

#pragma unroll 1
    for (int jt = 0; jt < NT; jt++) {
        int j0 = jt * 64;
        if (jt + 1 < NT) {
            load_kv((jt + 1) & 1, (jt + 1) * 64);
            asm volatile("cp.async.wait_group 1;" ::: "memory");
        } else {
            asm volatile("cp.async.wait_group 0;" ::: "memory");
        }
        __syncthreads();

        if (j0 <= wrow_max) {
            uint32_t kh_b = smb + 32768 + (uint32_t)(jt & 1) * 32768u;
            uint32_t kl_b = kh_b + 8192;
            uint32_t vh_b = kh_b + 16384;
            uint32_t vl_b = kh_b + 24576;

            float s[8][4];
#pragma unroll
            for (int nt = 0; nt < 8; nt++)
#pragma unroll
                for (int e = 0; e < 4; e++) s[nt][e] = 0.0f;

#pragma unroll
            for (int kb = 0; kb < 4; kb++) {
                int krow = ((lane >> 4) & 1) * 8 + (lane & 7);
                int kcol = kb * 32 + ((lane >> 3) & 1) * 16;
#pragma unroll
                for (int ntp = 0; ntp < 4; ntp++) {
                    uint32_t off = SW128((uint32_t)((ntp * 16 + krow) * 128 + kcol));
                    uint32_t th[4], tl[4];
                    ldsm_x4(th, kh_b + off);
                    ldsm_x4(tl, kl_b + off);
                    mma_bf16(s[2*ntp],     qfh[kb], th);
                    mma_bf16(s[2*ntp],     qfh[kb], tl);
                    mma_bf16(s[2*ntp],     qfl[kb], th);
                    mma_bf16(s[2*ntp + 1], qfh[kb], th + 2);
                    mma_bf16(s[2*ntp + 1], qfh[kb], tl + 2);
                    mma_bf16(s[2*ntp + 1], qfl[kb], th + 2);
                }
            }

#pragma unroll
            for (int nt = 0; nt < 8; nt++)
#pragma unroll
                for (int e = 0; e < 4; e++) s[nt][e] *= 0.125f;

            if (j0 + 63 > i0 + wid * 16) {
#pragma unroll
                for (int nt = 0; nt < 8; nt++) {
                    int c = j0 + nt * 8 + tr * 2;
                    if (c > gr0)     s[nt][0] = -1e30f;
                    if (c + 1 > gr0) s[nt][1] = -1e30f;
                    if (c > gr1)     s[nt][2] = -1e30f;
                    if (c + 1 > gr1) s[nt][3] = -1e30f;
                }
            }

            float mx0 = -1e30f, mx1 = -1e30f;
#pragma unroll
            for (int nt = 0; nt < 8; nt++) {
                mx0 = fmaxf(mx0, fmaxf(s[nt][0], s[nt][1]));
                mx1 = fmaxf(mx1, fmaxf(s[nt][2], s[nt][3]));
            }
            mx0 = fmaxf(mx0, __shfl_xor_sync(0xffffffffu, mx0, 1));
            mx0 = fmaxf(mx0, __shfl_xor_sync(0xffffffffu, mx0, 2));
            mx1 = fmaxf(mx1, __shfl_xor_sync(0xffffffffu, mx1, 1));
            mx1 = fmaxf(mx1, __shfl_xor_sync(0xffffffffu, mx1, 2));

            float mn0 = fmaxf(m0, mx0), mn1 = fmaxf(m1, mx1);
            float al0 = __expf(m0 - mn0), al1 = __expf(m1 - mn1);
            m0 = mn0; m1 = mn1;

            float sum0 = 0.0f, sum1 = 0.0f;
#pragma unroll
            for (int nt = 0; nt < 8; nt++) {
                s[nt][0] = __expf(s[nt][0] - mn0); sum0 += s[nt][0];
                s[nt][1] = __expf(s[nt][1] - mn0); sum0 += s[nt][1];
                s[nt][2] = __expf(s[nt][2] - mn1); sum1 += s[nt][2];
                s[nt][3] = __expf(s[nt][3] - mn1); sum1 += s[nt][3];
            }
            sum0 += __shfl_xor_sync(0xffffffffu, sum0, 1);
            sum0 += __shfl_xor_sync(0xffffffffu, sum0, 2);
            sum1 += __shfl_xor_sync(0xffffffffu, sum1, 1);
            sum1 += __shfl_xor_sync(0xffffffffu, sum1, 2);
            l0 = l0 * al0 + sum0;
            l1 = l1 * al1 + sum1;
#pragma unroll
            for (int dt = 0; dt < 8; dt++) {
                o[dt][0] *= al0; o[dt][1] *= al0;
                o[dt][2] *= al1; o[dt][3] *= al1;
            }

#pragma unroll
            for (int kb = 0; kb < 4; kb++) {
                uint32_t pah[4], pal[4];
                pack_pair(s[2*kb][0],     s[2*kb][1],     pah[0], pal[0]);
                pack_pair(s[2*kb][2],     s[2*kb][3],     pah[1], pal[1]);
                pack_pair(s[2*kb + 1][0], s[2*kb + 1][1], pah[2], pal[2]);
                pack_pair(s[2*kb + 1][2], s[2*kb + 1][3], pah[3], pal[3]);

                int vrow = kb * 16 + ((lane >> 3) & 1) * 8 + (lane & 7);
                int vcolb = ((lane >> 4) & 1) * 16;
#pragma unroll
                for (int dtp = 0; dtp < 4; dtp++) {
                    uint32_t off = SW128((uint32_t)(vrow * 128 + dtp * 32 + vcolb));
                    uint32_t th[4], tl[4];
                    ldsm_x4_t(th, vh_b + off);
                    ldsm_x4_t(tl, vl_b + off);
                    mma_bf16(o[2*dtp],     pah, th);
                    mma_bf16(o[2*dtp],     pal, th);
                    mma_bf16(o[2*dtp],     pah, tl);
                    mma_bf16(o[2*dtp + 1], pah, th + 2);
                    mma_bf16(o[2*dtp + 1], pal, th + 2);
                    mma_bf16(o[2*dtp + 1], pah, tl + 2);
                }
            }
        }
        __syncthreads();
    }

    float inv0 = 1.0f / l0, inv1 = 1.0f / l1;
    int b = bh >> 4, h = bh & 15;
#pragma unroll
    for (int dt = 0; dt < 8; dt++) {
        int col = h * 64 + dt * 8 + tr * 2;
        float y00 = o[dt][0] * inv0, y01 = o[dt][1] * inv0;
        float y10 = o[dt][2] * inv1, y11 = o[dt][3] * inv1;
        uint32_t h0, lo0, h1, lo1;
        pack_pair(y00, y01, h0, lo0);
        pack_pair(y10, y11, h1, lo1);
        size_t o0 = (size_t)(b * T_ + gr0) * C_ + col;
        size_t o1 = (size_t)(b * T_ + gr1) * C_ + col;
        *(uint32_t*)(Oh + o0) = h0;
        *(uint32_t*)(Ol + o0) = lo0;
        *(uint32_t*)(Oh + o1) = h1;
        *(uint32_t*)(Ol + o1) = lo1;
    }
}

// ---------------------------------------------------------------------------

extern "C" void kernel_launch(void* const* d_in, const int* in_sizes, int n_in,
                              void* d_out, int out_size)
{
    const float* x      = (const float*)d_in[0];
    const float* cosT   = (const float*)d_in[1];
    const float* sinT   = (const float*)d_in[2];
    const float* W_attn = (const float*)d_in[3];
    const float* b_attn = (const float*)d_in[4];
    const float* W_proj = (const float*)d_in[5];
    const float* b_proj = (const float*)d_in[6];
    float* out = (float*)d_out;

    float* qkv;
    __nv_bfloat16 *xh, *xl, *wah, *wal, *wph, *wpl, *ath, *atl;
    __nv_bfloat16 *qh, *ql, *kh, *kl, *vh, *vl;
    cudaGetSymbolAddress((void**)&qkv, g_qkv);
    cudaGetSymbolAddress((void**)&xh,  g_xh);
    cudaGetSymbolAddress((void**)&xl,  g_xl);
    cudaGetSymbolAddress((void**)&wah, g_wah);
    cudaGetSymbolAddress((void**)&wal, g_wal);
    cudaGetSymbolAddress((void**)&wph, g_wph);
    cudaGetSymbolAddress((void**)&wpl, g_wpl);
    cudaGetSymbolAddress((void**)&ath, g_ath);
    cudaGetSymbolAddress((void**)&atl, g_atl);
    cudaGetSymbolAddress((void**)&qh,  g_qh);
    cudaGetSymbolAddress((void**)&ql,  g_ql);
    cudaGetSymbolAddress((void**)&kh,  g_kh);
    cudaGetSymbolAddress((void**)&kl,  g_kl);
    cudaGetSymbolAddress((void**)&vh,  g_vh);
    cudaGetSymbolAddress((void**)&vl,  g_vl);

    const int GEMM_SMEM = 2 * STAGE_B;  // 81920
    cudaFuncSetAttribute(gemm_mma_kernel,
                         cudaFuncAttributeMaxDynamicSharedMemorySize, GEMM_SMEM);
    const int ATTN_SMEM = 98304;
    cudaFuncSetAttribute(attn_mma_kernel,
                         cudaFuncAttributeMaxDynamicSharedMemorySize, ATTN_SMEM);

    // 0) splits
    split_kernel<<<BT_ * C_ / 1024, 256>>>(x, xh, xl);
    splitT_kernel<<<dim3(3 * C_ / 32, C_ / 32), 256>>>(W_attn, wah, wal, C_, 3 * C_);
    splitT_kernel<<<dim3(C_ / 32, C_ / 32), 256>>>(W_proj, wph, wpl, C_, C_);

    // 1) QKV GEMM (tensor cores)
    gemm_mma_kernel<<<dim3(3 * C_ / 128, BT_ / 128), 256, GEMM_SMEM>>>(
        xh, xl, wah, wal, b_attn, qkv, BT_, 3 * C_, C_);

    // 2) RMSNorm + rotary + scatter to split bf16 Q/K/V
    rmsrot_kernel<<<(B_ * T_ * H_) / 8, 256>>>(qkv, cosT, sinT,
                                               qh, ql, kh, kl, vh, vl);

    // 3) Causal flash attention (tensor cores, split bf16)
    attn_mma_kernel<<<dim3(T_ / 128, B_ * H_), 256, ATTN_SMEM>>>(
        qh, ql, kh, kl, vh, vl, ath, atl);

    // 4) proj GEMM (tensor cores)
    gemm_mma_kernel<<<dim3(C_ / 128, BT_ / 128), 256, GEMM_SMEM>>>(
        ath, atl, wph, wpl, b_proj, out, BT_, C_, C_);
}